// round 6
// baseline (speedup 1.0000x reference)
#include <cuda_runtime.h>
#include <cuda_bf16.h>
#include <cstdint>

#define B__   256
#define NTOK  196
#define CDIM  256
#define NH    8
#define HDIM  32
#define MROWS (B__ * NTOK)          // 50176 = 392*128
#define KEXT  768                   // 3*256 split-bf16 K
#define QSCALE 0.17677669529663687f // 1/sqrt(32)

typedef unsigned long long ull;

// ---------------- scratch (device globals) ----------------
__device__ float g_q[MROWS * CDIM];
__device__ float g_k[MROWS * CDIM];
__device__ float g_v[MROWS * CDIM];
__device__ float g_o[MROWS * CDIM];
__device__ __nv_bfloat16 g_xb[(size_t)MROWS * KEXT]; // x split  [Ah, Al, Ah]
__device__ __nv_bfloat16 g_ob[(size_t)MROWS * KEXT]; // attn-out split
__device__ __nv_bfloat16 g_wq[768 * KEXT];           // qkv_w split [Bh, Bh, Bl]
__device__ __nv_bfloat16 g_wp[256 * KEXT];           // proj_w split

// ---------------- small PTX helpers ----------------
__device__ __forceinline__ uint32_t s2u(const void* p) {
    return (uint32_t)__cvta_generic_to_shared(p);
}
#define CP16(dst, src) \
    asm volatile("cp.async.ca.shared.global [%0], [%1], 16;" :: "r"(dst), "l"(src))
#define CP_COMMIT() asm volatile("cp.async.commit_group;" ::: "memory")
#define CP_WAIT(n)  asm volatile("cp.async.wait_group %0;" :: "n"(n) : "memory")

#define LDSM4(r0, r1, r2, r3, addr) \
    asm volatile("ldmatrix.sync.aligned.m8n8.x4.shared.b16 {%0,%1,%2,%3}, [%4];" \
                 : "=r"(r0), "=r"(r1), "=r"(r2), "=r"(r3) : "r"(addr))

#define MMA16816(d, a, b0, b1) \
    asm volatile("mma.sync.aligned.m16n8k16.row.col.f32.bf16.bf16.f32 " \
                 "{%0,%1,%2,%3}, {%4,%5,%6,%7}, {%8,%9}, {%0,%1,%2,%3};" \
                 : "+f"((d)[0]), "+f"((d)[1]), "+f"((d)[2]), "+f"((d)[3]) \
                 : "r"((a)[0]), "r"((a)[1]), "r"((a)[2]), "r"((a)[3]), \
                   "r"(b0), "r"(b1))

// ---------------- split-bf16 conversion ----------------
__device__ __forceinline__ uint32_t pk2(float x, float y) {
    __nv_bfloat162 t = __float22bfloat162_rn(make_float2(x, y));
    return *(uint32_t*)&t;
}
// activations: [M][256] f32 -> [M][768] bf16 as {hi, lo, hi}
template <int SRC>
__global__ __launch_bounds__(256) void conv_act(const float* __restrict__ srcp,
                                                __nv_bfloat16* __restrict__ dst) {
    const float* src = (SRC == 0) ? srcp : g_o;
    int i = blockIdx.x * 256 + threadIdx.x;       // float4 index, total MROWS*64
    float4 v = ((const float4*)src)[i];
    int row = i >> 6, c = (i & 63) << 2;
    __nv_bfloat16 hx = __float2bfloat16(v.x), hy = __float2bfloat16(v.y);
    __nv_bfloat16 hz = __float2bfloat16(v.z), hw = __float2bfloat16(v.w);
    float lx = v.x - __bfloat162float(hx), ly = v.y - __bfloat162float(hy);
    float lz = v.z - __bfloat162float(hz), lw = v.w - __bfloat162float(hw);
    uint2 hi; hi.x = pk2(__bfloat162float(hx), __bfloat162float(hy));
              hi.y = pk2(__bfloat162float(hz), __bfloat162float(hw));
    uint2 lo; lo.x = pk2(lx, ly); lo.y = pk2(lz, lw);
    __nv_bfloat16* base = dst + (size_t)row * KEXT + c;
    *(uint2*)(base)       = hi;
    *(uint2*)(base + 256) = lo;
    *(uint2*)(base + 512) = hi;
}
// weights: [N][256] f32 -> [N][768] bf16 as {hi, hi, lo}
__global__ __launch_bounds__(256) void conv_wgt(const float* __restrict__ src,
                                                __nv_bfloat16* __restrict__ dst) {
    int i = blockIdx.x * 256 + threadIdx.x;
    float4 v = ((const float4*)src)[i];
    int row = i >> 6, c = (i & 63) << 2;
    __nv_bfloat16 hx = __float2bfloat16(v.x), hy = __float2bfloat16(v.y);
    __nv_bfloat16 hz = __float2bfloat16(v.z), hw = __float2bfloat16(v.w);
    float lx = v.x - __bfloat162float(hx), ly = v.y - __bfloat162float(hy);
    float lz = v.z - __bfloat162float(hz), lw = v.w - __bfloat162float(hw);
    uint2 hi; hi.x = pk2(__bfloat162float(hx), __bfloat162float(hy));
              hi.y = pk2(__bfloat162float(hz), __bfloat162float(hw));
    uint2 lo; lo.x = pk2(lx, ly); lo.y = pk2(lz, lw);
    __nv_bfloat16* base = dst + (size_t)row * KEXT + c;
    *(uint2*)(base)       = hi;
    *(uint2*)(base + 256) = hi;
    *(uint2*)(base + 512) = lo;
}

// ---------------- HMMA bf16 GEMM (mma.sync.m16n8k16) ----------------
// Y[r][c] = sum_k A'[r][k] * B'[c][k]  (+bias), K = 768 split-bf16
// MODE 0: A=g_xb, B=g_wq (cols = nt*128..+127 of 768) -> scatter q/k/v
// MODE 1: A=g_ob, B=g_wp -> out
// CTA 128x128, BK=32, 24 stages, cp.async double-buffer, 8 warps 2(m)x4(n).
#define BK    32
#define LDS_S 40                    // smem row stride in bf16 (padded)
#define NSTG  (KEXT / BK)           // 24

template <int MODE>
__global__ __launch_bounds__(256) void hmma_gemm(const float* __restrict__ bias,
                                                 float* __restrict__ out) {
    __shared__ __align__(16) __nv_bfloat16 As[2][128 * LDS_S];
    __shared__ __align__(16) __nv_bfloat16 Bs[2][128 * LDS_S];

    const int tid = threadIdx.x, lane = tid & 31, wid = tid >> 5;
    const int nt = blockIdx.x;
    const int rowBase = blockIdx.y << 7;
    const int colBase = nt << 7;

    const __nv_bfloat16* Ag = ((MODE == 0) ? g_xb : g_ob) + (size_t)rowBase * KEXT;
    const __nv_bfloat16* Bg = ((MODE == 0) ? g_wq : g_wp) + (size_t)colBase * KEXT;

    // loader: 512 16B-chunks per operand per stage; thread t does chunks t, t+256
    const int c0r = tid >> 2, c0c = (tid & 3) << 3;           // chunk tid
    const int c1r = (tid + 256) >> 2, c1c = c0c;              // chunk tid+256

#define LOADSTAGE(s, buf) do { \
    const int kt = (s) * BK; \
    CP16(s2u(&As[buf][c0r * LDS_S + c0c]), Ag + (size_t)c0r * KEXT + kt + c0c); \
    CP16(s2u(&As[buf][c1r * LDS_S + c1c]), Ag + (size_t)c1r * KEXT + kt + c1c); \
    CP16(s2u(&Bs[buf][c0r * LDS_S + c0c]), Bg + (size_t)c0r * KEXT + kt + c0c); \
    CP16(s2u(&Bs[buf][c1r * LDS_S + c1c]), Bg + (size_t)c1r * KEXT + kt + c1c); \
    CP_COMMIT(); \
} while (0)

    // warp tiling: 2 (m) x 4 (n); warp tile 64m x 32n
    const int wm = wid & 1, wn = wid >> 1;
    const int Am = wm * 64, Bn = wn * 32;
    // ldmatrix lane->tile coords
    const int a_row = lane & 15;
    const int a_ko  = (lane >> 4) << 3;
    const int b_n   = ((lane >> 4) << 3) + (lane & 7);
    const int b_ko  = ((lane >> 3) & 1) << 3;

    float d[4][4][4];
#pragma unroll
    for (int i = 0; i < 4; i++)
#pragma unroll
        for (int j = 0; j < 4; j++)
#pragma unroll
            for (int e = 0; e < 4; e++) d[i][j][e] = 0.f;

    LOADSTAGE(0, 0);

    for (int s = 0; s < NSTG; s++) {
        const int buf = s & 1;
        if (s + 1 < NSTG) { LOADSTAGE(s + 1, buf ^ 1); CP_WAIT(1); }
        else              { CP_WAIT(0); }
        __syncthreads();

#pragma unroll
        for (int kk = 0; kk < BK; kk += 16) {
            uint32_t a[4][4];
#pragma unroll
            for (int mi = 0; mi < 4; mi++) {
                const uint32_t ad =
                    s2u(&As[buf][(Am + mi * 16 + a_row) * LDS_S + kk + a_ko]);
                LDSM4(a[mi][0], a[mi][1], a[mi][2], a[mi][3], ad);
            }
            uint32_t b[2][4];
#pragma unroll
            for (int nb = 0; nb < 2; nb++) {
                const uint32_t bd =
                    s2u(&Bs[buf][(Bn + nb * 16 + b_n) * LDS_S + kk + b_ko]);
                LDSM4(b[nb][0], b[nb][1], b[nb][2], b[nb][3], bd);
            }
#pragma unroll
            for (int mi = 0; mi < 4; mi++)
#pragma unroll
                for (int nj = 0; nj < 4; nj++)
                    MMA16816(d[mi][nj], a[mi], b[nj >> 1][(nj & 1) * 2],
                             b[nj >> 1][(nj & 1) * 2 + 1]);
        }
        __syncthreads();
    }
#undef LOADSTAGE

    // epilogue
    const int erow = lane >> 2;          // 0..7
    const int ecol = (lane & 3) << 1;    // 0,2,4,6
#pragma unroll
    for (int mi = 0; mi < 4; mi++) {
#pragma unroll
        for (int nj = 0; nj < 4; nj++) {
            const int col = colBase + Bn + nj * 8 + ecol;   // even, pair in same head
            const float b0 = bias[col], b1 = bias[col + 1];
#pragma unroll
            for (int half = 0; half < 2; half++) {
                const int r = rowBase + Am + mi * 16 + erow + half * 8;
                float2 v;
                v.x = d[mi][nj][half * 2 + 0] + b0;
                v.y = d[mi][nj][half * 2 + 1] + b1;
                if (MODE == 0) {
                    const int sel = col >> 8, h = (col >> 5) & 7, dd = col & 31;
                    const int bb = r / NTOK, nn = r - bb * NTOK;
                    float* dst = (sel == 0) ? g_q : (sel == 1) ? g_k : g_v;
                    if (sel == 0) { v.x *= QSCALE; v.y *= QSCALE; }
                    *(float2*)&dst[(((size_t)bb * NH + h) * NTOK + nn) * HDIM + dd] = v;
                } else {
                    *(float2*)&out[(size_t)r * CDIM + col] = v;
                }
            }
        }
    }
}

// ---------------------------------------------------------------------------
// Fused attention (unchanged): one CTA per (b, h), FFMA2 QK^T.
// ---------------------------------------------------------------------------
#define FMA2(d, a, b, c) \
    asm("fma.rn.f32x2 %0, %1, %2, %3;" : "=l"(d) : "l"(a), "l"(b), "l"(c))
__device__ __forceinline__ ull pack2(float lo, float hi) {
    ull r; asm("mov.b64 %0, {%1, %2};" : "=l"(r) : "f"(lo), "f"(hi)); return r;
}
__device__ __forceinline__ float2 unpack2(ull v) {
    float2 f; asm("mov.b64 {%0, %1}, %2;" : "=f"(f.x), "=f"(f.y) : "l"(v)); return f;
}

#define SM_KT 0
#define SM_VS 6400
#define SM_BC 12672
#define SM_PB 13856
#define SM_QS 20256
#define SM_FLOATS 21280
#define ATTN_SMEM_BYTES (SM_FLOATS * 4)

__global__ __launch_bounds__(256) void attn_kernel(
    const float* __restrict__ mask, const float* __restrict__ bias_table,
    const int* __restrict__ rel_index)
{
    extern __shared__ float sm[];
    float* Kt = sm + SM_KT;
    float* Vs = sm + SM_VS;
    float* Bc = sm + SM_BC;

    const int tid = threadIdx.x;
    const int lane = tid & 31, warp = tid >> 5;
    const int bh = blockIdx.x;
    const int b = bh >> 3, h = bh & 7;
    const size_t base = (size_t)bh * (NTOK * HDIM);

    for (int idx = tid; idx < NTOK * HDIM; idx += 256) {
        const int m = idx >> 5, d = idx & 31;
        Kt[d * 200 + m] = g_k[base + idx];
        Vs[idx] = g_v[base + idx];
    }
    for (int i = tid; i < 1183; i += 256) Bc[i] = bias_table[i * NH + h];
    __syncthreads();

    const float4* Kt4 = (const float4*)Kt;
    const int* riB = rel_index;
    const float* mkB = mask + (size_t)(b & 63) * (NTOK * NTOK);
    const bool g2 = (lane < 17);
    float* Qw = sm + SM_QS + warp * 128;
    float* Pw = sm + SM_PB + warp * 800;
    const float4* Qw4 = (const float4*)Qw;

    for (int row0 = warp * 4; row0 < NTOK; row0 += 32) {
#pragma unroll
        for (int r = 0; r < 4; r++)
            Qw[r * 32 + lane] = g_q[base + (size_t)(row0 + r) * HDIM + lane];
        __syncwarp();

        ull S2[4][4] = {};
#pragma unroll
        for (int d4 = 0; d4 < 8; d4++) {
            float qa[4][4];
#pragma unroll
            for (int r = 0; r < 4; r++) {
                const float4 t = Qw4[r * 8 + d4];
                qa[r][0] = t.x; qa[r][1] = t.y; qa[r][2] = t.z; qa[r][3] = t.w;
            }
#pragma unroll
            for (int dd = 0; dd < 4; dd++) {
                const int d = d4 * 4 + dd;
                const float4 k0 = Kt4[d * 50 + lane];
                const ull kp0 = pack2(k0.x, k0.y);
                const ull kp1 = pack2(k0.z, k0.w);
                ull kp2 = 0, kp3 = 0;
                if (g2) {
                    const float4 k1 = Kt4[d * 50 + 32 + lane];
                    kp2 = pack2(k1.x, k1.y);
                    kp3 = pack2(k1.z, k1.w);
                }
#pragma unroll
                for (int r = 0; r < 4; r++) {
                    const ull q2 = pack2(qa[r][dd], qa[r][dd]);
                    FMA2(S2[r][0], q2, kp0, S2[r][0]);
                    FMA2(S2[r][1], q2, kp1, S2[r][1]);
                    if (g2) {
                        FMA2(S2[r][2], q2, kp2, S2[r][2]);
                        FMA2(S2[r][3], q2, kp3, S2[r][3]);
                    }
                }
            }
        }

        float S[4][8];
#pragma unroll
        for (int r = 0; r < 4; r++) {
#pragma unroll
            for (int p = 0; p < 4; p++) {
                const float2 u = unpack2(S2[r][p]);
                S[r][p * 2] = u.x; S[r][p * 2 + 1] = u.y;
            }
        }

#pragma unroll
        for (int r = 0; r < 4; r++) {
            const int row = row0 + r;
            {
                const int4   i0 = ((const int4*)(riB + row * NTOK))[lane];
                const float4 m0 = ((const float4*)(mkB + (size_t)row * NTOK))[lane];
                S[r][0] += Bc[i0.x] + m0.x; S[r][1] += Bc[i0.y] + m0.y;
                S[r][2] += Bc[i0.z] + m0.z; S[r][3] += Bc[i0.w] + m0.w;
                if (g2) {
                    const int4   i1 = ((const int4*)(riB + row * NTOK))[32 + lane];
                    const float4 m1 = ((const float4*)(mkB + (size_t)row * NTOK))[32 + lane];
                    S[r][4] += Bc[i1.x] + m1.x; S[r][5] += Bc[i1.y] + m1.y;
                    S[r][6] += Bc[i1.z] + m1.z; S[r][7] += Bc[i1.w] + m1.w;
                }
            }
            float mx = fmaxf(fmaxf(S[r][0], S[r][1]), fmaxf(S[r][2], S[r][3]));
            if (g2) mx = fmaxf(mx, fmaxf(fmaxf(S[r][4], S[r][5]), fmaxf(S[r][6], S[r][7])));
#pragma unroll
            for (int off = 16; off; off >>= 1)
                mx = fmaxf(mx, __shfl_xor_sync(0xffffffffu, mx, off));

            float sum = 0.f;
#pragma unroll
            for (int j = 0; j < 4; j++) { S[r][j] = __expf(S[r][j] - mx); sum += S[r][j]; }
            if (g2) {
#pragma unroll
                for (int j = 4; j < 8; j++) { S[r][j] = __expf(S[r][j] - mx); sum += S[r][j]; }
            }
#pragma unroll
            for (int off = 16; off; off >>= 1)
                sum += __shfl_xor_sync(0xffffffffu, sum, off);
            const float inv = 1.0f / sum;
#pragma unroll
            for (int j = 0; j < 8; j++) S[r][j] *= inv;

            ((float4*)(Pw + r * 200))[lane] = make_float4(S[r][0], S[r][1], S[r][2], S[r][3]);
            if (g2)
                ((float4*)(Pw + r * 200))[32 + lane] = make_float4(S[r][4], S[r][5], S[r][6], S[r][7]);
        }
        __syncwarp();

        float acc[4] = {0.f, 0.f, 0.f, 0.f};
#pragma unroll 7
        for (int g = 0; g < 49; g++) {
            const float* vr = Vs + g * 128 + lane;
            const float v0 = vr[0], v1 = vr[32], v2 = vr[64], v3 = vr[96];
#pragma unroll
            for (int r = 0; r < 4; r++) {
                const float4 p = ((const float4*)(Pw + r * 200))[g];
                acc[r] += p.x * v0 + p.y * v1 + p.z * v2 + p.w * v3;
            }
        }
#pragma unroll
        for (int r = 0; r < 4; r++)
            g_o[((size_t)b * NTOK + row0 + r) * CDIM + h * HDIM + lane] = acc[r];
        __syncwarp();
    }
}

// ---------------------------------------------------------------------------
extern "C" void kernel_launch(void* const* d_in, const int* in_sizes, int n_in,
                              void* d_out, int out_size)
{
    const float* x          = (const float*)d_in[0];
    const float* mask       = (const float*)d_in[1];
    const float* qkv_w      = (const float*)d_in[2];
    const float* qkv_b      = (const float*)d_in[3];
    const float* proj_w     = (const float*)d_in[4];
    const float* proj_b     = (const float*)d_in[5];
    const float* bias_table = (const float*)d_in[6];
    const int*   rel_index  = (const int*)d_in[7];
    float* out = (float*)d_out;

    cudaFuncSetAttribute(attn_kernel,
                         cudaFuncAttributeMaxDynamicSharedMemorySize, ATTN_SMEM_BYTES);

    __nv_bfloat16 *xb, *ob, *wq, *wp;
    cudaGetSymbolAddress((void**)&xb, g_xb);
    cudaGetSymbolAddress((void**)&ob, g_ob);
    cudaGetSymbolAddress((void**)&wq, g_wq);
    cudaGetSymbolAddress((void**)&wp, g_wp);

    // 1) split-bf16 conversions of x and weights
    conv_act<0><<<MROWS * 64 / 256, 256>>>(x, xb);
    conv_wgt<<<768 * 64 / 256, 256>>>(qkv_w, wq);
    conv_wgt<<<256 * 64 / 256, 256>>>(proj_w, wp);
    // 2) QKV projection (HMMA): N tiles 0..5 -> q (scaled), k, v
    hmma_gemm<0><<<dim3(6, MROWS / 128), 256>>>(qkv_b, nullptr);
    // 3) fused window attention -> g_o
    attn_kernel<<<B__ * NH, 256, ATTN_SMEM_BYTES>>>(mask, bias_table, rel_index);
    // 4) split-bf16 conversion of attention output
    conv_act<1><<<MROWS * 64 / 256, 256>>>(nullptr, ob);
    // 5) output projection (HMMA)
    hmma_gemm<1><<<dim3(2, MROWS / 128), 256>>>(proj_b, out);
}

// round 7
// speedup vs baseline: 1.6478x; 1.6478x over previous
#include <cuda_runtime.h>
#include <cuda_bf16.h>
#include <cstdint>

#define B__   256
#define NTOK  196
#define CDIM  256
#define NH    8
#define HDIM  32
#define MROWS (B__ * NTOK)          // 50176 = 392*128
#define KEXT  768                   // 3*256 split-bf16 K
#define QSCALE 0.17677669529663687f // 1/sqrt(32)

typedef unsigned long long ull;

// ---------------- scratch (device globals) ----------------
__device__ float g_q[MROWS * CDIM];
__device__ float g_k[MROWS * CDIM];
__device__ float g_v[MROWS * CDIM];
__device__ float g_o[MROWS * CDIM];
__device__ __nv_bfloat16 g_xb[(size_t)MROWS * KEXT]; // x split  [Ah, Al, Ah]
__device__ __nv_bfloat16 g_ob[(size_t)MROWS * KEXT]; // attn-out split
__device__ __nv_bfloat16 g_wq[768 * KEXT];           // qkv_w split [Bh, Bh, Bl]
__device__ __nv_bfloat16 g_wp[256 * KEXT];           // proj_w split

// ---------------- small PTX helpers ----------------
__device__ __forceinline__ uint32_t s2u(const void* p) {
    return (uint32_t)__cvta_generic_to_shared(p);
}
#define CP16(dst, src) \
    asm volatile("cp.async.ca.shared.global [%0], [%1], 16;" :: "r"(dst), "l"(src))
#define CP_COMMIT() asm volatile("cp.async.commit_group;" ::: "memory")
#define CP_WAIT(n)  asm volatile("cp.async.wait_group %0;" :: "n"(n) : "memory")

#define LDSM4(r0, r1, r2, r3, addr) \
    asm volatile("ldmatrix.sync.aligned.m8n8.x4.shared.b16 {%0,%1,%2,%3}, [%4];" \
                 : "=r"(r0), "=r"(r1), "=r"(r2), "=r"(r3) : "r"(addr))

#define MMA16816(d, a, b0, b1) \
    asm volatile("mma.sync.aligned.m16n8k16.row.col.f32.bf16.bf16.f32 " \
                 "{%0,%1,%2,%3}, {%4,%5,%6,%7}, {%8,%9}, {%0,%1,%2,%3};" \
                 : "+f"((d)[0]), "+f"((d)[1]), "+f"((d)[2]), "+f"((d)[3]) \
                 : "r"((a)[0]), "r"((a)[1]), "r"((a)[2]), "r"((a)[3]), \
                   "r"(b0), "r"(b1))

// ---------------- split-bf16 conversion ----------------
__device__ __forceinline__ uint32_t pk2(float x, float y) {
    __nv_bfloat162 t = __float22bfloat162_rn(make_float2(x, y));
    return *(uint32_t*)&t;
}
// activations: [M][256] f32 -> [M][768] bf16 as {hi, lo, hi}
template <int SRC>
__global__ __launch_bounds__(256) void conv_act(const float* __restrict__ srcp,
                                                __nv_bfloat16* __restrict__ dst) {
    const float* src = (SRC == 0) ? srcp : g_o;
    int i = blockIdx.x * 256 + threadIdx.x;       // float4 index, total MROWS*64
    float4 v = ((const float4*)src)[i];
    int row = i >> 6, c = (i & 63) << 2;
    __nv_bfloat16 hx = __float2bfloat16(v.x), hy = __float2bfloat16(v.y);
    __nv_bfloat16 hz = __float2bfloat16(v.z), hw = __float2bfloat16(v.w);
    float lx = v.x - __bfloat162float(hx), ly = v.y - __bfloat162float(hy);
    float lz = v.z - __bfloat162float(hz), lw = v.w - __bfloat162float(hw);
    uint2 hi; hi.x = pk2(__bfloat162float(hx), __bfloat162float(hy));
              hi.y = pk2(__bfloat162float(hz), __bfloat162float(hw));
    uint2 lo; lo.x = pk2(lx, ly); lo.y = pk2(lz, lw);
    __nv_bfloat16* base = dst + (size_t)row * KEXT + c;
    *(uint2*)(base)       = hi;
    *(uint2*)(base + 256) = lo;
    *(uint2*)(base + 512) = hi;
}
// weights: [N][256] f32 -> [N][768] bf16 as {hi, hi, lo}
__global__ __launch_bounds__(256) void conv_wgt(const float* __restrict__ src,
                                                __nv_bfloat16* __restrict__ dst) {
    int i = blockIdx.x * 256 + threadIdx.x;
    float4 v = ((const float4*)src)[i];
    int row = i >> 6, c = (i & 63) << 2;
    __nv_bfloat16 hx = __float2bfloat16(v.x), hy = __float2bfloat16(v.y);
    __nv_bfloat16 hz = __float2bfloat16(v.z), hw = __float2bfloat16(v.w);
    float lx = v.x - __bfloat162float(hx), ly = v.y - __bfloat162float(hy);
    float lz = v.z - __bfloat162float(hz), lw = v.w - __bfloat162float(hw);
    uint2 hi; hi.x = pk2(__bfloat162float(hx), __bfloat162float(hy));
              hi.y = pk2(__bfloat162float(hz), __bfloat162float(hw));
    uint2 lo; lo.x = pk2(lx, ly); lo.y = pk2(lz, lw);
    __nv_bfloat16* base = dst + (size_t)row * KEXT + c;
    *(uint2*)(base)       = hi;
    *(uint2*)(base + 256) = hi;
    *(uint2*)(base + 512) = lo;
}

// ---------------- HMMA bf16 GEMM (mma.sync.m16n8k16) ----------------
// Y[r][c] = sum_k A'[r][k] * B'[c][k]  (+bias), K = 768 split-bf16
// MODE 0: A=g_xb, B=g_wq -> scatter q/k/v ; MODE 1: A=g_ob, B=g_wp -> out
// CTA 128x128, BK=32, 24 stages, 4-deep cp.async pipeline, one barrier/stage,
// 8 warps 2(m)x4(n), __launch_bounds__(256,2) for 2 CTAs/SM.
#define BK     32
#define LDS_S  40                   // smem row stride in bf16 (padded)
#define NSTG   (KEXT / BK)          // 24
#define STAGEF (128 * LDS_S)        // bf16 per operand per stage (5120)
#define GSMEM  (4 * STAGEF * 2 * 2) // 81920 bytes

template <int MODE>
__global__ __launch_bounds__(256, 2) void hmma_gemm(const float* __restrict__ bias,
                                                    float* __restrict__ out) {
    extern __shared__ __align__(16) __nv_bfloat16 smb[];
    __nv_bfloat16* As = smb;                 // [4][STAGEF]
    __nv_bfloat16* Bs = smb + 4 * STAGEF;    // [4][STAGEF]

    const int tid = threadIdx.x, lane = tid & 31, wid = tid >> 5;
    const int nt = blockIdx.x;
    const int rowBase = blockIdx.y << 7;
    const int colBase = nt << 7;

    const __nv_bfloat16* Ag = ((MODE == 0) ? g_xb : g_ob) + (size_t)rowBase * KEXT;
    const __nv_bfloat16* Bg = ((MODE == 0) ? g_wq : g_wp) + (size_t)colBase * KEXT;

    // loader: 512 16B-chunks per operand per stage; thread t does chunks t, t+256
    const int c0r = tid >> 2, c0c = (tid & 3) << 3;           // chunk tid
    const int c1r = (tid + 256) >> 2, c1c = c0c;              // chunk tid+256

#define LOADSTAGE(s) do { \
    const int kt = (s) * BK; \
    __nv_bfloat16* ap = As + ((s) & 3) * STAGEF; \
    __nv_bfloat16* bp = Bs + ((s) & 3) * STAGEF; \
    CP16(s2u(ap + c0r * LDS_S + c0c), Ag + (size_t)c0r * KEXT + kt + c0c); \
    CP16(s2u(ap + c1r * LDS_S + c1c), Ag + (size_t)c1r * KEXT + kt + c1c); \
    CP16(s2u(bp + c0r * LDS_S + c0c), Bg + (size_t)c0r * KEXT + kt + c0c); \
    CP16(s2u(bp + c1r * LDS_S + c1c), Bg + (size_t)c1r * KEXT + kt + c1c); \
    CP_COMMIT(); \
} while (0)

    // warp tiling: 2 (m) x 4 (n); warp tile 64m x 32n
    const int wm = wid & 1, wn = wid >> 1;
    const int Am = wm * 64, Bn = wn * 32;
    // ldmatrix lane->tile coords
    const int a_row = lane & 15;
    const int a_ko  = (lane >> 4) << 3;
    const int b_n   = ((lane >> 4) << 3) + (lane & 7);
    const int b_ko  = ((lane >> 3) & 1) << 3;

    float d[4][4][4];
#pragma unroll
    for (int i = 0; i < 4; i++)
#pragma unroll
        for (int j = 0; j < 4; j++)
#pragma unroll
            for (int e = 0; e < 4; e++) d[i][j][e] = 0.f;

    LOADSTAGE(0);
    LOADSTAGE(1);
    LOADSTAGE(2);

    for (int s = 0; s < NSTG; s++) {
        if (s < NSTG - 2)       CP_WAIT(2);
        else if (s == NSTG - 2) CP_WAIT(1);
        else                    CP_WAIT(0);
        __syncthreads();

        const __nv_bfloat16* abuf = As + (s & 3) * STAGEF;
        const __nv_bfloat16* bbuf = Bs + (s & 3) * STAGEF;
#pragma unroll
        for (int kk = 0; kk < BK; kk += 16) {
            uint32_t a[4][4];
#pragma unroll
            for (int mi = 0; mi < 4; mi++) {
                const uint32_t ad =
                    s2u(abuf + (Am + mi * 16 + a_row) * LDS_S + kk + a_ko);
                LDSM4(a[mi][0], a[mi][1], a[mi][2], a[mi][3], ad);
            }
            uint32_t b[2][4];
#pragma unroll
            for (int nb = 0; nb < 2; nb++) {
                const uint32_t bd =
                    s2u(bbuf + (Bn + nb * 16 + b_n) * LDS_S + kk + b_ko);
                LDSM4(b[nb][0], b[nb][1], b[nb][2], b[nb][3], bd);
            }
#pragma unroll
            for (int mi = 0; mi < 4; mi++)
#pragma unroll
                for (int nj = 0; nj < 4; nj++)
                    MMA16816(d[mi][nj], a[mi], b[nj >> 1][(nj & 1) * 2],
                             b[nj >> 1][(nj & 1) * 2 + 1]);
        }
        // issue load for stage s+3 (buffer (s+3)&3 == (s-1)&3, safe: all warps
        // passed this stage's barrier, so none is still reading stage s-1)
        if (s + 3 < NSTG) LOADSTAGE(s + 3);
    }
#undef LOADSTAGE

    // epilogue
    const int erow = lane >> 2;          // 0..7
    const int ecol = (lane & 3) << 1;    // 0,2,4,6
#pragma unroll
    for (int mi = 0; mi < 4; mi++) {
#pragma unroll
        for (int nj = 0; nj < 4; nj++) {
            const int col = colBase + Bn + nj * 8 + ecol;   // even, pair in same head
            const float b0 = bias[col], b1 = bias[col + 1];
#pragma unroll
            for (int half = 0; half < 2; half++) {
                const int r = rowBase + Am + mi * 16 + erow + half * 8;
                float2 v;
                v.x = d[mi][nj][half * 2 + 0] + b0;
                v.y = d[mi][nj][half * 2 + 1] + b1;
                if (MODE == 0) {
                    const int sel = col >> 8, h = (col >> 5) & 7, dd = col & 31;
                    const int bb = r / NTOK, nn = r - bb * NTOK;
                    float* dst = (sel == 0) ? g_q : (sel == 1) ? g_k : g_v;
                    if (sel == 0) { v.x *= QSCALE; v.y *= QSCALE; }
                    *(float2*)&dst[(((size_t)bb * NH + h) * NTOK + nn) * HDIM + dd] = v;
                } else {
                    *(float2*)&out[(size_t)r * CDIM + col] = v;
                }
            }
        }
    }
}

// ---------------------------------------------------------------------------
// Fused attention (unchanged): one CTA per (b, h), FFMA2 QK^T.
// ---------------------------------------------------------------------------
#define FMA2(d, a, b, c) \
    asm("fma.rn.f32x2 %0, %1, %2, %3;" : "=l"(d) : "l"(a), "l"(b), "l"(c))
__device__ __forceinline__ ull pack2(float lo, float hi) {
    ull r; asm("mov.b64 %0, {%1, %2};" : "=l"(r) : "f"(lo), "f"(hi)); return r;
}
__device__ __forceinline__ float2 unpack2(ull v) {
    float2 f; asm("mov.b64 {%0, %1}, %2;" : "=f"(f.x), "=f"(f.y) : "l"(v)); return f;
}

#define SM_KT 0
#define SM_VS 6400
#define SM_BC 12672
#define SM_PB 13856
#define SM_QS 20256
#define SM_FLOATS 21280
#define ATTN_SMEM_BYTES (SM_FLOATS * 4)

__global__ __launch_bounds__(256) void attn_kernel(
    const float* __restrict__ mask, const float* __restrict__ bias_table,
    const int* __restrict__ rel_index)
{
    extern __shared__ float sm[];
    float* Kt = sm + SM_KT;
    float* Vs = sm + SM_VS;
    float* Bc = sm + SM_BC;

    const int tid = threadIdx.x;
    const int lane = tid & 31, warp = tid >> 5;
    const int bh = blockIdx.x;
    const int b = bh >> 3, h = bh & 7;
    const size_t base = (size_t)bh * (NTOK * HDIM);

    for (int idx = tid; idx < NTOK * HDIM; idx += 256) {
        const int m = idx >> 5, d = idx & 31;
        Kt[d * 200 + m] = g_k[base + idx];
        Vs[idx] = g_v[base + idx];
    }
    for (int i = tid; i < 1183; i += 256) Bc[i] = bias_table[i * NH + h];
    __syncthreads();

    const float4* Kt4 = (const float4*)Kt;
    const int* riB = rel_index;
    const float* mkB = mask + (size_t)(b & 63) * (NTOK * NTOK);
    const bool g2 = (lane < 17);
    float* Qw = sm + SM_QS + warp * 128;
    float* Pw = sm + SM_PB + warp * 800;
    const float4* Qw4 = (const float4*)Qw;

    for (int row0 = warp * 4; row0 < NTOK; row0 += 32) {
#pragma unroll
        for (int r = 0; r < 4; r++)
            Qw[r * 32 + lane] = g_q[base + (size_t)(row0 + r) * HDIM + lane];
        __syncwarp();

        ull S2[4][4] = {};
#pragma unroll
        for (int d4 = 0; d4 < 8; d4++) {
            float qa[4][4];
#pragma unroll
            for (int r = 0; r < 4; r++) {
                const float4 t = Qw4[r * 8 + d4];
                qa[r][0] = t.x; qa[r][1] = t.y; qa[r][2] = t.z; qa[r][3] = t.w;
            }
#pragma unroll
            for (int dd = 0; dd < 4; dd++) {
                const int d = d4 * 4 + dd;
                const float4 k0 = Kt4[d * 50 + lane];
                const ull kp0 = pack2(k0.x, k0.y);
                const ull kp1 = pack2(k0.z, k0.w);
                ull kp2 = 0, kp3 = 0;
                if (g2) {
                    const float4 k1 = Kt4[d * 50 + 32 + lane];
                    kp2 = pack2(k1.x, k1.y);
                    kp3 = pack2(k1.z, k1.w);
                }
#pragma unroll
                for (int r = 0; r < 4; r++) {
                    const ull q2 = pack2(qa[r][dd], qa[r][dd]);
                    FMA2(S2[r][0], q2, kp0, S2[r][0]);
                    FMA2(S2[r][1], q2, kp1, S2[r][1]);
                    if (g2) {
                        FMA2(S2[r][2], q2, kp2, S2[r][2]);
                        FMA2(S2[r][3], q2, kp3, S2[r][3]);
                    }
                }
            }
        }

        float S[4][8];
#pragma unroll
        for (int r = 0; r < 4; r++) {
#pragma unroll
            for (int p = 0; p < 4; p++) {
                const float2 u = unpack2(S2[r][p]);
                S[r][p * 2] = u.x; S[r][p * 2 + 1] = u.y;
            }
        }

#pragma unroll
        for (int r = 0; r < 4; r++) {
            const int row = row0 + r;
            {
                const int4   i0 = ((const int4*)(riB + row * NTOK))[lane];
                const float4 m0 = ((const float4*)(mkB + (size_t)row * NTOK))[lane];
                S[r][0] += Bc[i0.x] + m0.x; S[r][1] += Bc[i0.y] + m0.y;
                S[r][2] += Bc[i0.z] + m0.z; S[r][3] += Bc[i0.w] + m0.w;
                if (g2) {
                    const int4   i1 = ((const int4*)(riB + row * NTOK))[32 + lane];
                    const float4 m1 = ((const float4*)(mkB + (size_t)row * NTOK))[32 + lane];
                    S[r][4] += Bc[i1.x] + m1.x; S[r][5] += Bc[i1.y] + m1.y;
                    S[r][6] += Bc[i1.z] + m1.z; S[r][7] += Bc[i1.w] + m1.w;
                }
            }
            float mx = fmaxf(fmaxf(S[r][0], S[r][1]), fmaxf(S[r][2], S[r][3]));
            if (g2) mx = fmaxf(mx, fmaxf(fmaxf(S[r][4], S[r][5]), fmaxf(S[r][6], S[r][7])));
#pragma unroll
            for (int off = 16; off; off >>= 1)
                mx = fmaxf(mx, __shfl_xor_sync(0xffffffffu, mx, off));

            float sum = 0.f;
#pragma unroll
            for (int j = 0; j < 4; j++) { S[r][j] = __expf(S[r][j] - mx); sum += S[r][j]; }
            if (g2) {
#pragma unroll
                for (int j = 4; j < 8; j++) { S[r][j] = __expf(S[r][j] - mx); sum += S[r][j]; }
            }
#pragma unroll
            for (int off = 16; off; off >>= 1)
                sum += __shfl_xor_sync(0xffffffffu, sum, off);
            const float inv = 1.0f / sum;
#pragma unroll
            for (int j = 0; j < 8; j++) S[r][j] *= inv;

            ((float4*)(Pw + r * 200))[lane] = make_float4(S[r][0], S[r][1], S[r][2], S[r][3]);
            if (g2)
                ((float4*)(Pw + r * 200))[32 + lane] = make_float4(S[r][4], S[r][5], S[r][6], S[r][7]);
        }
        __syncwarp();

        float acc[4] = {0.f, 0.f, 0.f, 0.f};
#pragma unroll 7
        for (int g = 0; g < 49; g++) {
            const float* vr = Vs + g * 128 + lane;
            const float v0 = vr[0], v1 = vr[32], v2 = vr[64], v3 = vr[96];
#pragma unroll
            for (int r = 0; r < 4; r++) {
                const float4 p = ((const float4*)(Pw + r * 200))[g];
                acc[r] += p.x * v0 + p.y * v1 + p.z * v2 + p.w * v3;
            }
        }
#pragma unroll
        for (int r = 0; r < 4; r++)
            g_o[((size_t)b * NTOK + row0 + r) * CDIM + h * HDIM + lane] = acc[r];
        __syncwarp();
    }
}

// ---------------------------------------------------------------------------
extern "C" void kernel_launch(void* const* d_in, const int* in_sizes, int n_in,
                              void* d_out, int out_size)
{
    const float* x          = (const float*)d_in[0];
    const float* mask       = (const float*)d_in[1];
    const float* qkv_w      = (const float*)d_in[2];
    const float* qkv_b      = (const float*)d_in[3];
    const float* proj_w     = (const float*)d_in[4];
    const float* proj_b     = (const float*)d_in[5];
    const float* bias_table = (const float*)d_in[6];
    const int*   rel_index  = (const int*)d_in[7];
    float* out = (float*)d_out;

    cudaFuncSetAttribute(attn_kernel,
                         cudaFuncAttributeMaxDynamicSharedMemorySize, ATTN_SMEM_BYTES);
    cudaFuncSetAttribute(hmma_gemm<0>,
                         cudaFuncAttributeMaxDynamicSharedMemorySize, GSMEM);
    cudaFuncSetAttribute(hmma_gemm<1>,
                         cudaFuncAttributeMaxDynamicSharedMemorySize, GSMEM);

    __nv_bfloat16 *xb, *ob, *wq, *wp;
    cudaGetSymbolAddress((void**)&xb, g_xb);
    cudaGetSymbolAddress((void**)&ob, g_ob);
    cudaGetSymbolAddress((void**)&wq, g_wq);
    cudaGetSymbolAddress((void**)&wp, g_wp);

    // 1) split-bf16 conversions of x and weights
    conv_act<0><<<MROWS * 64 / 256, 256>>>(x, xb);
    conv_wgt<<<768 * 64 / 256, 256>>>(qkv_w, wq);
    conv_wgt<<<256 * 64 / 256, 256>>>(proj_w, wp);
    // 2) QKV projection (HMMA): N tiles 0..5 -> q (scaled), k, v
    hmma_gemm<0><<<dim3(6, MROWS / 128), 256, GSMEM>>>(qkv_b, nullptr);
    // 3) fused window attention -> g_o
    attn_kernel<<<B__ * NH, 256, ATTN_SMEM_BYTES>>>(mask, bias_table, rel_index);
    // 4) split-bf16 conversion of attention output
    conv_act<1><<<MROWS * 64 / 256, 256>>>(nullptr, ob);
    // 5) output projection (HMMA)
    hmma_gemm<1><<<dim3(2, MROWS / 128), 256, GSMEM>>>(proj_b, out);
}